// round 16
// baseline (speedup 1.0000x reference)
#include <cuda_runtime.h>
#include <cuda_bf16.h>
#include <cstdint>

#define N_NODES 100000
#define E_EDGES 500000

// ---------------------------------------------------------------------------
// Device scratch
// ---------------------------------------------------------------------------
__device__ uint4 g_UVq4[(size_t)N_NODES * 64];  // int16 UV rows: [node][512] (b1 folded into U)
__device__ float g_sc[N_NODES * 16];            // per (node, 32-col chunk) scale
__device__ uint4 g_nBhi4[16384];                // node B: 8 chunks x 128x128 bf16
__device__ uint4 g_nBlo4[16384];
__device__ uint4 g_eBhi4[4096];                 // edge B (W2): 2 chunks
__device__ uint4 g_eBlo4[4096];
__device__ int   g_idx64;

#define CHUNK_U4 2048   // 128x128 bf16 = 2048 uint4 (16 uint4 per 128-row)

#define PITCH_A  528    // A row: 256 bf16 + pad
#define EP       144    // B quarter row: 64 bf16 (128B) + 16 pad
#define QB       (128 * EP)   // 18432
#define SPITCH   68     // staging pitch in uint32 (64 + 4 pad)

// ---------------- node smem layout ----------------
#define N_AHI  0
#define N_ALO  67584
#define N_B0H  (2 * 67584)           // 135168
#define SM_N   (N_B0H + 4 * QB)      // 208896

// ---------------- edge smem layout ----------------
#define E_SRC  0
#define E_DST  512
#define E_AHI  1536
#define E_ALO  (1536 + 67584)
#define E_B0H  (1536 + 2 * 67584)    // 136704
#define SM_E   (E_B0H + 4 * QB)      // 210432
#define STG_PITCH 132

__device__ __forceinline__ uint32_t smem_u32(const void* p) {
    uint32_t a;
    asm("{ .reg .u64 t; cvta.to.shared.u64 t, %1; cvt.u32.u64 %0, t; }" : "=r"(a) : "l"(p));
    return a;
}

__device__ __forceinline__ void ldsm_x4(uint32_t* r, uint32_t addr) {
    asm volatile("ldmatrix.sync.aligned.m8n8.x4.shared.b16 {%0,%1,%2,%3}, [%4];"
                 : "=r"(r[0]), "=r"(r[1]), "=r"(r[2]), "=r"(r[3]) : "r"(addr));
}

__device__ __forceinline__ void mma16816(float* d, const uint32_t* a, const uint32_t* b) {
    asm volatile(
        "mma.sync.aligned.m16n8k16.row.col.f32.bf16.bf16.f32 "
        "{%0,%1,%2,%3},{%4,%5,%6,%7},{%8,%9},{%0,%1,%2,%3};"
        : "+f"(d[0]), "+f"(d[1]), "+f"(d[2]), "+f"(d[3])
        : "r"(a[0]), "r"(a[1]), "r"(a[2]), "r"(a[3]), "r"(b[0]), "r"(b[1]));
}

__device__ __forceinline__ void cpasync16(uint32_t saddr, const void* g) {
    asm volatile("cp.async.ca.shared.global [%0], [%1], 16;" :: "r"(saddr), "l"(g));
}
__device__ __forceinline__ void cp_commit() { asm volatile("cp.async.commit_group;"); }
__device__ __forceinline__ void cp_wait0()  { asm volatile("cp.async.wait_group 0;" ::: "memory"); }
__device__ __forceinline__ void cp_wait1()  { asm volatile("cp.async.wait_group 1;" ::: "memory"); }

// packed bf16 split
__device__ __forceinline__ void split2(float a, float b, uint32_t& hi, uint32_t& lo) {
    uint32_t h;
    asm("cvt.rn.bf16x2.f32 %0, %1, %2;" : "=r"(h) : "f"(b), "f"(a));
    float ah = __uint_as_float(h << 16);
    float bh = __uint_as_float(h & 0xFFFF0000u);
    uint32_t l;
    asm("cvt.rn.bf16x2.f32 %0, %1, %2;" : "=r"(l) : "f"(b - bh), "f"(a - ah));
    hi = h;
    lo = l;
}

__device__ __forceinline__ void dq8(uint4 p, float s, float* f) {
    f[0] = (float)((short)(p.x & 0xFFFF)) * s; f[1] = (float)(((int)p.x) >> 16) * s;
    f[2] = (float)((short)(p.y & 0xFFFF)) * s; f[3] = (float)(((int)p.y) >> 16) * s;
    f[4] = (float)((short)(p.z & 0xFFFF)) * s; f[5] = (float)(((int)p.z) >> 16) * s;
    f[6] = (float)((short)(p.w & 0xFFFF)) * s; f[7] = (float)(((int)p.w) >> 16) * s;
}

__device__ __forceinline__ uint32_t pk16(float a, float b) {
    int ia = __float2int_rn(a), ib = __float2int_rn(b);
    return (uint32_t)(ia & 0xFFFF) | ((uint32_t)ib << 16);
}

// ---------------------------------------------------------------------------
// detect edge_index dtype (int64 vs int32)
// ---------------------------------------------------------------------------
__global__ void detect_kernel(const unsigned* __restrict__ ei) {
    if (threadIdx.x == 0 && blockIdx.x == 0) {
        int ok = 1;
        #pragma unroll 1
        for (int i = 0; i < 256; i++)
            if (ei[2 * i + 1] != 0u) { ok = 0; break; }
        g_idx64 = ok;
    }
}

// ---------------------------------------------------------------------------
// prep: split weights into bf16 hi/lo chunk blobs [chunk][row][k] (128x128)
// ---------------------------------------------------------------------------
__global__ void prep_kernel(const float* __restrict__ W1, const float* __restrict__ W2) {
    int idx = blockIdx.x * blockDim.x + threadIdx.x;
    float v;
    uint32_t off;
    __nv_bfloat16 *dh, *dl;
    if (idx < 131072) {
        int j = idx >> 8, k = idx & 255;
        v = (j < 256) ? W1[j * 512 + k] : W1[(j - 256) * 512 + 256 + k];
        int nc = j >> 7, row = j & 127, kc = k >> 7, kp = k & 127;
        off = (uint32_t)(kc * 4 + nc) * 16384u + row * 128 + kp;
        dh = (__nv_bfloat16*)g_nBhi4; dl = (__nv_bfloat16*)g_nBlo4;
    } else {
        int e = idx - 131072;
        if (e >= 32768) return;
        int n = e >> 8, k = e & 255;
        v = W2[n * 256 + k];
        int kc = k >> 7, kp = k & 127;
        off = (uint32_t)kc * 16384u + n * 128 + kp;
        dh = (__nv_bfloat16*)g_eBhi4; dl = (__nv_bfloat16*)g_eBlo4;
    }
    __nv_bfloat16 h = __float2bfloat16_rn(v);
    dh[off] = h;
    dl[off] = __float2bfloat16_rn(v - __bfloat162float(h));
}

// ---------------------------------------------------------------------------
// shared helpers
// ---------------------------------------------------------------------------
// async load one 64-k B quarter (hi+lo): 128 rows x 8 uint4 each
__device__ __forceinline__ void load_Bq(uint32_t dstH, uint32_t dstL,
                                        const uint4* blobH, const uint4* blobL,
                                        int h, int tid) {
    #pragma unroll
    for (int i = 0; i < 4; i++) {
        int idx = i * 256 + tid;          // 0..1023
        int n = idx >> 3, j = idx & 7;
        uint32_t d = n * EP + j * 16;
        cpasync16(dstH + d, blobH + n * 16 + h * 8 + j);
        cpasync16(dstL + d, blobL + n * 16 + h * 8 + j);
    }
    cp_commit();
}

// 4 k-steps (64 k) of 3-pass bf16 mma
__device__ __forceinline__ void mma_q(float d[4][4][4],
                                      uint32_t aHi, uint32_t aLo,
                                      uint32_t bHi, uint32_t bLo) {
    #pragma unroll
    for (int ks = 0; ks < 4; ks++) {
        uint32_t Ah[4][4], Al[4][4], Bh[2][4], Bl[2][4];
        #pragma unroll
        for (int f = 0; f < 4; f++) {
            ldsm_x4(Ah[f], aHi + f * (16 * PITCH_A) + ks * 32);
            ldsm_x4(Al[f], aLo + f * (16 * PITCH_A) + ks * 32);
        }
        #pragma unroll
        for (int gp = 0; gp < 2; gp++) {
            ldsm_x4(Bh[gp], bHi + gp * (16 * EP) + ks * 32);
            ldsm_x4(Bl[gp], bLo + gp * (16 * EP) + ks * 32);
        }
        #pragma unroll
        for (int f = 0; f < 4; f++)
            #pragma unroll
            for (int g = 0; g < 4; g++) {
                const uint32_t* bh = &Bh[g >> 1][(g & 1) * 2];
                const uint32_t* bl = &Bl[g >> 1][(g & 1) * 2];
                mma16816(d[f][g], Ah[f], bh);
                mma16816(d[f][g], Ah[f], bl);
                mma16816(d[f][g], Al[f], bh);
            }
    }
}

__device__ __forceinline__ uint32_t a_lane_base(uint32_t smA, int wm, int lane) {
    int row = wm * 64 + (lane & 7) + ((lane >> 3) & 1) * 8;
    return smA + row * PITCH_A + ((lane >> 4) & 1) * 16;
}
__device__ __forceinline__ uint32_t b_lane_off(int wn, int lane) {
    int n = wn * 32 + (lane & 7) + ((lane >> 4) & 1) * 8;
    return (uint32_t)(n * EP + ((lane >> 3) & 1) * 16);
}

// ---------------------------------------------------------------------------
// node kernel (R15, unchanged): UV tile (b1 folded) -> int16, coalesced epilogue
// ---------------------------------------------------------------------------
__global__ void __launch_bounds__(256, 1) node_mma(const float* __restrict__ Z,
                                                   const float* __restrict__ b1) {
    extern __shared__ char sm[];
    const uint32_t smb = smem_u32(sm);
    const int tid = threadIdx.x, lane = tid & 31, wid = tid >> 5;
    const int wm = wid & 1, wn = wid >> 1;
    const int mbase = blockIdx.x * 128;

    load_Bq(smb + N_B0H, smb + N_B0H + QB, g_nBhi4, g_nBlo4, 0, tid);

    {
        const int lrow = tid >> 3;
        const int lk = (tid & 7) * 4;
        #pragma unroll 1
        for (int s = 0; s < 4; s++) {
            int row = s * 32 + lrow;
            int gr = min(mbase + row, N_NODES - 1);
            const float* zr = Z + (size_t)gr * 256;
            char* ah = sm + N_AHI + row * PITCH_A;
            char* al = sm + N_ALO + row * PITCH_A;
            #pragma unroll
            for (int i = 0; i < 8; i++) {
                int k = lk + i * 32;
                float4 z4 = *(const float4*)(zr + k);
                uint32_t h0, l0, h1, l1;
                split2(z4.x, z4.y, h0, l0);
                split2(z4.z, z4.w, h1, l1);
                *(uint2*)(ah + k * 2) = make_uint2(h0, h1);
                *(uint2*)(al + k * 2) = make_uint2(l0, l1);
            }
        }
    }

    const uint32_t aHi = a_lane_base(smb + N_AHI, wm, lane);
    const uint32_t aLo = a_lane_base(smb + N_ALO, wm, lane);
    const uint32_t bOff = b_lane_off(wn, lane);
    const uint32_t bufH[2] = {smb + N_B0H, smb + N_B0H + 2 * QB};

    float d[4][4][4];
    #pragma unroll
    for (int f = 0; f < 4; f++)
        #pragma unroll
        for (int g = 0; g < 4; g++)
            #pragma unroll
            for (int c = 0; c < 4; c++) d[f][g][c] = 0.f;

    #pragma unroll 1
    for (int t = 0; t < 16; t++) {
        if (t < 15) {
            int tn = t + 1;
            int nc2 = tn >> 2, qk2 = tn & 3;
            int ch = (qk2 >> 1) * 4 + nc2;
            load_Bq(bufH[tn & 1], bufH[tn & 1] + QB,
                    g_nBhi4 + ch * CHUNK_U4, g_nBlo4 + ch * CHUNK_U4, qk2 & 1, tid);
            cp_wait1();
        } else {
            cp_wait0();
        }
        __syncthreads();
        const int qk = t & 3;
        mma_q(d, aHi + qk * 128, aLo + qk * 128,
              bufH[t & 1] + bOff, bufH[t & 1] + QB + bOff);

        if (qk == 3) {
            const int nc = t >> 2;
            if (nc < 2) {
                #pragma unroll
                for (int g = 0; g < 4; g++) {
                    int col = nc * 128 + wn * 32 + g * 8 + (lane & 3) * 2;
                    float2 bb = *(const float2*)(b1 + col);
                    #pragma unroll
                    for (int f = 0; f < 4; f++) {
                        d[f][g][0] += bb.x; d[f][g][1] += bb.y;
                        d[f][g][2] += bb.x; d[f][g][3] += bb.y;
                    }
                }
            }
            __syncthreads();
            uint32_t* S = (uint32_t*)(sm + N_B0H + (t & 1) * 2 * QB);
            #pragma unroll
            for (int f = 0; f < 4; f++) {
                float m0 = 0.f, m1 = 0.f;
                #pragma unroll
                for (int g = 0; g < 4; g++) {
                    m0 = fmaxf(m0, fmaxf(fabsf(d[f][g][0]), fabsf(d[f][g][1])));
                    m1 = fmaxf(m1, fmaxf(fabsf(d[f][g][2]), fabsf(d[f][g][3])));
                }
                m0 = fmaxf(m0, __shfl_xor_sync(0xFFFFFFFFu, m0, 1));
                m0 = fmaxf(m0, __shfl_xor_sync(0xFFFFFFFFu, m0, 2));
                m1 = fmaxf(m1, __shfl_xor_sync(0xFFFFFFFFu, m1, 1));
                m1 = fmaxf(m1, __shfl_xor_sync(0xFFFFFFFFu, m1, 2));
                float s0 = (m0 > 1e-30f) ? m0 * (1.f / 32704.f) : 1.f;
                float s1 = (m1 > 1e-30f) ? m1 * (1.f / 32704.f) : 1.f;
                float i0 = 1.f / s0, i1 = 1.f / s1;
                int r0 = wm * 64 + f * 16 + (lane >> 2);
                int r1 = r0 + 8;
                if ((lane & 3) == 0) {
                    if (mbase + r0 < N_NODES) g_sc[(mbase + r0) * 16 + nc * 4 + wn] = s0;
                    if (mbase + r1 < N_NODES) g_sc[(mbase + r1) * 16 + nc * 4 + wn] = s1;
                }
                #pragma unroll
                for (int g = 0; g < 4; g++) {
                    int cu = wn * 16 + g * 4 + (lane & 3);
                    S[r0 * SPITCH + cu] = pk16(d[f][g][0] * i0, d[f][g][1] * i0);
                    S[r1 * SPITCH + cu] = pk16(d[f][g][2] * i1, d[f][g][3] * i1);
                    d[f][g][0] = d[f][g][1] = d[f][g][2] = d[f][g][3] = 0.f;
                }
            }
            __syncthreads();
            #pragma unroll
            for (int i = 0; i < 8; i++) {
                int idx = i * 256 + tid;
                int row = idx >> 4, c = idx & 15;
                int node = mbase + row;
                if (node < N_NODES) {
                    const uint32_t* sp = S + row * SPITCH + c * 4;
                    uint4 v = make_uint4(sp[0], sp[1], sp[2], sp[3]);
                    g_UVq4[(size_t)node * 64 + nc * 16 + c] = v;
                }
            }
        }
        __syncthreads();
    }
}

// ---------------------------------------------------------------------------
// edge kernel: quarter-pipelined A-stage (LDG regs ahead of mma), streaming out
// ---------------------------------------------------------------------------
__global__ void __launch_bounds__(256, 1) edge_mma(const void* __restrict__ EI,
                                                   const float* __restrict__ b2,
                                                   float* __restrict__ out) {
    extern __shared__ char sm[];
    const uint32_t smb = smem_u32(sm);
    int* ssrc = (int*)(sm + E_SRC);
    int* sdst = (int*)(sm + E_DST);
    const int tid = threadIdx.x, lane = tid & 31, wid = tid >> 5;
    const int wm = wid & 1, wn = wid >> 1;
    const int ebase = blockIdx.x * 128;
    const int lrow = tid >> 3;
    const int j = tid & 7;
    const int jj = j >> 2;

    // prefetch B quarter 0
    load_Bq(smb + E_B0H, smb + E_B0H + QB, g_eBhi4, g_eBlo4, 0, tid);

    if (tid < 128) {
        int e = ebase + tid;
        long long s = 0, dd = 0;
        if (e < E_EDGES) {
            if (g_idx64) {
                const long long* p = (const long long*)EI;
                s = p[e]; dd = p[e + E_EDGES];
            } else {
                const int* p = (const int*)EI;
                s = p[e]; dd = p[e + E_EDGES];
            }
        }
        ssrc[tid] = min(max((int)s, 0), N_NODES - 1);
        sdst[tid] = min(max((int)dd, 0), N_NODES - 1);
    }
    __syncthreads();

    // stage A quarter 0 synchronously
    {
        #pragma unroll
        for (int s = 0; s < 4; s++) {
            int row = s * 32 + lrow;
            int src = ssrc[row], dst = sdst[row];
            uint4 up = g_UVq4[(size_t)src * 64 + j];
            uint4 vp = g_UVq4[(size_t)dst * 64 + 32 + j];
            float su = g_sc[src * 16 + jj];
            float sv = g_sc[dst * 16 + 8 + jj];
            float uu[8], vv[8];
            dq8(up, su, uu);
            dq8(vp, sv, vv);
            uint4 hi, lo;
            split2(fmaxf(uu[0] + vv[0], 0.f), fmaxf(uu[1] + vv[1], 0.f), hi.x, lo.x);
            split2(fmaxf(uu[2] + vv[2], 0.f), fmaxf(uu[3] + vv[3], 0.f), hi.y, lo.y);
            split2(fmaxf(uu[4] + vv[4], 0.f), fmaxf(uu[5] + vv[5], 0.f), hi.z, lo.z);
            split2(fmaxf(uu[6] + vv[6], 0.f), fmaxf(uu[7] + vv[7], 0.f), hi.w, lo.w);
            *(uint4*)(sm + E_AHI + row * PITCH_A + j * 16) = hi;
            *(uint4*)(sm + E_ALO + row * PITCH_A + j * 16) = lo;
        }
    }

    const uint32_t aHi = a_lane_base(smb + E_AHI, wm, lane);
    const uint32_t aLo = a_lane_base(smb + E_ALO, wm, lane);
    const uint32_t bOff = b_lane_off(wn, lane);
    const uint32_t bufH[2] = {smb + E_B0H, smb + E_B0H + 2 * QB};

    float d[4][4][4];
    #pragma unroll
    for (int f = 0; f < 4; f++)
        #pragma unroll
        for (int g = 0; g < 4; g++)
            #pragma unroll
            for (int c = 0; c < 4; c++) d[f][g][c] = 0.f;

    #pragma unroll 1
    for (int t = 0; t < 4; t++) {
        cp_wait0();
        __syncthreads();

        // issue next-quarter gather loads into registers (latency hidden by mma)
        uint4 ur[4], vr[4];
        float su[4], sv[4];
        const int q = t + 1;
        if (t < 3) {
            #pragma unroll
            for (int s = 0; s < 4; s++) {
                int row = s * 32 + lrow;
                int src = ssrc[row], dst = sdst[row];
                ur[s] = g_UVq4[(size_t)src * 64 + q * 8 + j];
                vr[s] = g_UVq4[(size_t)dst * 64 + 32 + q * 8 + j];
                su[s] = g_sc[src * 16 + q * 2 + jj];
                sv[s] = g_sc[dst * 16 + 8 + q * 2 + jj];
            }
            // prefetch B quarter t+1
            load_Bq(bufH[q & 1], bufH[q & 1] + QB,
                    g_eBhi4 + (q >> 1) * CHUNK_U4, g_eBlo4 + (q >> 1) * CHUNK_U4,
                    q & 1, tid);
        }

        mma_q(d, aHi + t * 128, aLo + t * 128,
              bufH[t & 1] + bOff, bufH[t & 1] + QB + bOff);

        if (t < 3) {
            // finish staging quarter t+1
            #pragma unroll
            for (int s = 0; s < 4; s++) {
                int row = s * 32 + lrow;
                float uu[8], vv[8];
                dq8(ur[s], su[s], uu);
                dq8(vr[s], sv[s], vv);
                uint4 hi, lo;
                split2(fmaxf(uu[0] + vv[0], 0.f), fmaxf(uu[1] + vv[1], 0.f), hi.x, lo.x);
                split2(fmaxf(uu[2] + vv[2], 0.f), fmaxf(uu[3] + vv[3], 0.f), hi.y, lo.y);
                split2(fmaxf(uu[4] + vv[4], 0.f), fmaxf(uu[5] + vv[5], 0.f), hi.z, lo.z);
                split2(fmaxf(uu[6] + vv[6], 0.f), fmaxf(uu[7] + vv[7], 0.f), hi.w, lo.w);
                *(uint4*)(sm + E_AHI + row * PITCH_A + q * 128 + j * 16) = hi;
                *(uint4*)(sm + E_ALO + row * PITCH_A + q * 128 + j * 16) = lo;
            }
        }
    }

    // --- staged, coalesced epilogue with fused b2, streaming stores ---
    __syncthreads();
    float* stg = (float*)(sm + E_B0H);
    #pragma unroll
    for (int g = 0; g < 4; g++) {
        int col = wn * 32 + g * 8 + (lane & 3) * 2;
        #pragma unroll
        for (int f = 0; f < 4; f++) {
            int r0 = wm * 64 + f * 16 + (lane >> 2);
            *(float2*)(stg + r0 * STG_PITCH + col) = make_float2(d[f][g][0], d[f][g][1]);
            *(float2*)(stg + (r0 + 8) * STG_PITCH + col) = make_float2(d[f][g][2], d[f][g][3]);
        }
    }
    __syncthreads();
    {
        const int c = (tid & 31) * 4;
        float4 bb = *(const float4*)(b2 + c);
        #pragma unroll
        for (int i = 0; i < 16; i++) {
            int idx = i * 256 + tid;
            int row = idx >> 5;
            int e = ebase + row;
            if (e < E_EDGES) {
                float4 v = *(const float4*)(stg + row * STG_PITCH + c);
                float4 o = make_float4(v.x + bb.x, v.y + bb.y, v.z + bb.z, v.w + bb.w);
                __stcs((float4*)(out + (size_t)e * 128 + c), o);
            }
        }
    }
}

// ---------------------------------------------------------------------------
// launch — inputs resolved by unique element counts
// ---------------------------------------------------------------------------
extern "C" void kernel_launch(void* const* d_in, const int* in_sizes, int n_in,
                              void* d_out, int out_size) {
    const float* z = nullptr;
    const void* ei = nullptr;
    const float* W1 = nullptr;
    const float* b1 = nullptr;
    const float* W2 = nullptr;
    const float* b2 = nullptr;
    for (int i = 0; i < n_in; i++) {
        switch (in_sizes[i]) {
            case 25600000: z = (const float*)d_in[i]; break;
            case 1000000:  ei = d_in[i];              break;
            case 131072:   W1 = (const float*)d_in[i]; break;
            case 256:      b1 = (const float*)d_in[i]; break;
            case 32768:    W2 = (const float*)d_in[i]; break;
            case 128:      b2 = (const float*)d_in[i]; break;
            default: break;
        }
    }
    float* out = (float*)d_out;

    cudaFuncSetAttribute(node_mma, cudaFuncAttributeMaxDynamicSharedMemorySize, SM_N);
    cudaFuncSetAttribute(edge_mma, cudaFuncAttributeMaxDynamicSharedMemorySize, SM_E);

    detect_kernel<<<1, 32>>>((const unsigned*)ei);
    prep_kernel<<<640, 256>>>(W1, W2);
    node_mma<<<(N_NODES + 127) / 128, 256, SM_N>>>(z, b1);
    edge_mma<<<(E_EDGES + 127) / 128, 256, SM_E>>>(ei, b2, out);
}

// round 17
// speedup vs baseline: 1.0255x; 1.0255x over previous
#include <cuda_runtime.h>
#include <cuda_bf16.h>
#include <cstdint>

#define N_NODES 100000
#define E_EDGES 500000

// ---------------------------------------------------------------------------
// Device scratch
// ---------------------------------------------------------------------------
__device__ uint4 g_UVq4[(size_t)N_NODES * 64];  // int16 UV rows: [node][512] (b1 folded into U)
__device__ float g_sc[N_NODES * 16];            // per (node, 32-col chunk) scale
__device__ uint4 g_nBhi4[16384];                // node B: 8 chunks x 128x128 bf16
__device__ uint4 g_nBlo4[16384];
__device__ uint4 g_eBhi4[4096];                 // edge B (W2): 2 chunks
__device__ uint4 g_eBlo4[4096];
__device__ int   g_idx64;

#define CHUNK_U4 2048   // 128x128 bf16 = 2048 uint4 (16 uint4 per 128-row)

#define PITCH_A  528    // A row: 256 bf16 + pad
#define EP       144    // B quarter row: 64 bf16 (128B) + 16 pad
#define QB       (128 * EP)   // 18432
#define SPITCH   68     // staging pitch in uint32 (64 + 4 pad)

// ---------------- node smem layout ----------------
#define N_AHI  0
#define N_ALO  67584
#define N_B0H  (2 * 67584)           // 135168
#define SM_N   (N_B0H + 4 * QB)      // 208896

// ---------------- edge smem layout ----------------
#define E_SRC  0
#define E_DST  512
#define E_AHI  1536
#define E_ALO  (1536 + 67584)
#define E_B0H  (1536 + 2 * 67584)    // 136704
#define SM_E   (E_B0H + 4 * QB)      // 210432
#define STG_PITCH 132

__device__ __forceinline__ uint32_t smem_u32(const void* p) {
    uint32_t a;
    asm("{ .reg .u64 t; cvta.to.shared.u64 t, %1; cvt.u32.u64 %0, t; }" : "=r"(a) : "l"(p));
    return a;
}

__device__ __forceinline__ void ldsm_x4(uint32_t* r, uint32_t addr) {
    asm volatile("ldmatrix.sync.aligned.m8n8.x4.shared.b16 {%0,%1,%2,%3}, [%4];"
                 : "=r"(r[0]), "=r"(r[1]), "=r"(r[2]), "=r"(r[3]) : "r"(addr));
}

__device__ __forceinline__ void mma16816(float* d, const uint32_t* a, const uint32_t* b) {
    asm volatile(
        "mma.sync.aligned.m16n8k16.row.col.f32.bf16.bf16.f32 "
        "{%0,%1,%2,%3},{%4,%5,%6,%7},{%8,%9},{%0,%1,%2,%3};"
        : "+f"(d[0]), "+f"(d[1]), "+f"(d[2]), "+f"(d[3])
        : "r"(a[0]), "r"(a[1]), "r"(a[2]), "r"(a[3]), "r"(b[0]), "r"(b[1]));
}

__device__ __forceinline__ void cpasync16(uint32_t saddr, const void* g) {
    asm volatile("cp.async.ca.shared.global [%0], [%1], 16;" :: "r"(saddr), "l"(g));
}
__device__ __forceinline__ void cp_commit() { asm volatile("cp.async.commit_group;"); }
__device__ __forceinline__ void cp_wait0()  { asm volatile("cp.async.wait_group 0;" ::: "memory"); }
__device__ __forceinline__ void cp_wait1()  { asm volatile("cp.async.wait_group 1;" ::: "memory"); }

// packed bf16 split
__device__ __forceinline__ void split2(float a, float b, uint32_t& hi, uint32_t& lo) {
    uint32_t h;
    asm("cvt.rn.bf16x2.f32 %0, %1, %2;" : "=r"(h) : "f"(b), "f"(a));
    float ah = __uint_as_float(h << 16);
    float bh = __uint_as_float(h & 0xFFFF0000u);
    uint32_t l;
    asm("cvt.rn.bf16x2.f32 %0, %1, %2;" : "=r"(l) : "f"(b - bh), "f"(a - ah));
    hi = h;
    lo = l;
}

__device__ __forceinline__ void dq8(uint4 p, float s, float* f) {
    f[0] = (float)((short)(p.x & 0xFFFF)) * s; f[1] = (float)(((int)p.x) >> 16) * s;
    f[2] = (float)((short)(p.y & 0xFFFF)) * s; f[3] = (float)(((int)p.y) >> 16) * s;
    f[4] = (float)((short)(p.z & 0xFFFF)) * s; f[5] = (float)(((int)p.z) >> 16) * s;
    f[6] = (float)((short)(p.w & 0xFFFF)) * s; f[7] = (float)(((int)p.w) >> 16) * s;
}

__device__ __forceinline__ uint32_t pk16(float a, float b) {
    int ia = __float2int_rn(a), ib = __float2int_rn(b);
    return (uint32_t)(ia & 0xFFFF) | ((uint32_t)ib << 16);
}

// ---------------------------------------------------------------------------
// detect edge_index dtype (int64 vs int32)
// ---------------------------------------------------------------------------
__global__ void detect_kernel(const unsigned* __restrict__ ei) {
    if (threadIdx.x == 0 && blockIdx.x == 0) {
        int ok = 1;
        #pragma unroll 1
        for (int i = 0; i < 256; i++)
            if (ei[2 * i + 1] != 0u) { ok = 0; break; }
        g_idx64 = ok;
    }
}

// ---------------------------------------------------------------------------
// prep: split weights into bf16 hi/lo chunk blobs [chunk][row][k] (128x128)
// ---------------------------------------------------------------------------
__global__ void prep_kernel(const float* __restrict__ W1, const float* __restrict__ W2) {
    int idx = blockIdx.x * blockDim.x + threadIdx.x;
    float v;
    uint32_t off;
    __nv_bfloat16 *dh, *dl;
    if (idx < 131072) {
        int j = idx >> 8, k = idx & 255;
        v = (j < 256) ? W1[j * 512 + k] : W1[(j - 256) * 512 + 256 + k];
        int nc = j >> 7, row = j & 127, kc = k >> 7, kp = k & 127;
        off = (uint32_t)(kc * 4 + nc) * 16384u + row * 128 + kp;
        dh = (__nv_bfloat16*)g_nBhi4; dl = (__nv_bfloat16*)g_nBlo4;
    } else {
        int e = idx - 131072;
        if (e >= 32768) return;
        int n = e >> 8, k = e & 255;
        v = W2[n * 256 + k];
        int kc = k >> 7, kp = k & 127;
        off = (uint32_t)kc * 16384u + n * 128 + kp;
        dh = (__nv_bfloat16*)g_eBhi4; dl = (__nv_bfloat16*)g_eBlo4;
    }
    __nv_bfloat16 h = __float2bfloat16_rn(v);
    dh[off] = h;
    dl[off] = __float2bfloat16_rn(v - __bfloat162float(h));
}

// ---------------------------------------------------------------------------
// shared helpers
// ---------------------------------------------------------------------------
// async load one 64-k B quarter (hi+lo): 128 rows x 8 uint4 each
__device__ __forceinline__ void load_Bq(uint32_t dstH, uint32_t dstL,
                                        const uint4* blobH, const uint4* blobL,
                                        int h, int tid) {
    #pragma unroll
    for (int i = 0; i < 4; i++) {
        int idx = i * 256 + tid;          // 0..1023
        int n = idx >> 3, j = idx & 7;
        uint32_t d = n * EP + j * 16;
        cpasync16(dstH + d, blobH + n * 16 + h * 8 + j);
        cpasync16(dstL + d, blobL + n * 16 + h * 8 + j);
    }
    cp_commit();
}

// 4 k-steps (64 k) of 3-pass bf16 mma
__device__ __forceinline__ void mma_q(float d[4][4][4],
                                      uint32_t aHi, uint32_t aLo,
                                      uint32_t bHi, uint32_t bLo) {
    #pragma unroll
    for (int ks = 0; ks < 4; ks++) {
        uint32_t Ah[4][4], Al[4][4], Bh[2][4], Bl[2][4];
        #pragma unroll
        for (int f = 0; f < 4; f++) {
            ldsm_x4(Ah[f], aHi + f * (16 * PITCH_A) + ks * 32);
            ldsm_x4(Al[f], aLo + f * (16 * PITCH_A) + ks * 32);
        }
        #pragma unroll
        for (int gp = 0; gp < 2; gp++) {
            ldsm_x4(Bh[gp], bHi + gp * (16 * EP) + ks * 32);
            ldsm_x4(Bl[gp], bLo + gp * (16 * EP) + ks * 32);
        }
        #pragma unroll
        for (int f = 0; f < 4; f++)
            #pragma unroll
            for (int g = 0; g < 4; g++) {
                const uint32_t* bh = &Bh[g >> 1][(g & 1) * 2];
                const uint32_t* bl = &Bl[g >> 1][(g & 1) * 2];
                mma16816(d[f][g], Ah[f], bh);
                mma16816(d[f][g], Ah[f], bl);
                mma16816(d[f][g], Al[f], bh);
            }
    }
}

__device__ __forceinline__ uint32_t a_lane_base(uint32_t smA, int wm, int lane) {
    int row = wm * 64 + (lane & 7) + ((lane >> 3) & 1) * 8;
    return smA + row * PITCH_A + ((lane >> 4) & 1) * 16;
}
__device__ __forceinline__ uint32_t b_lane_off(int wn, int lane) {
    int n = wn * 32 + (lane & 7) + ((lane >> 4) & 1) * 8;
    return (uint32_t)(n * EP + ((lane >> 3) & 1) * 16);
}

// ---------------------------------------------------------------------------
// node kernel (R15, unchanged): UV tile (b1 folded) -> int16, coalesced epilogue
// ---------------------------------------------------------------------------
__global__ void __launch_bounds__(256, 1) node_mma(const float* __restrict__ Z,
                                                   const float* __restrict__ b1) {
    extern __shared__ char sm[];
    const uint32_t smb = smem_u32(sm);
    const int tid = threadIdx.x, lane = tid & 31, wid = tid >> 5;
    const int wm = wid & 1, wn = wid >> 1;
    const int mbase = blockIdx.x * 128;

    load_Bq(smb + N_B0H, smb + N_B0H + QB, g_nBhi4, g_nBlo4, 0, tid);

    {
        const int lrow = tid >> 3;
        const int lk = (tid & 7) * 4;
        #pragma unroll 1
        for (int s = 0; s < 4; s++) {
            int row = s * 32 + lrow;
            int gr = min(mbase + row, N_NODES - 1);
            const float* zr = Z + (size_t)gr * 256;
            char* ah = sm + N_AHI + row * PITCH_A;
            char* al = sm + N_ALO + row * PITCH_A;
            #pragma unroll
            for (int i = 0; i < 8; i++) {
                int k = lk + i * 32;
                float4 z4 = *(const float4*)(zr + k);
                uint32_t h0, l0, h1, l1;
                split2(z4.x, z4.y, h0, l0);
                split2(z4.z, z4.w, h1, l1);
                *(uint2*)(ah + k * 2) = make_uint2(h0, h1);
                *(uint2*)(al + k * 2) = make_uint2(l0, l1);
            }
        }
    }

    const uint32_t aHi = a_lane_base(smb + N_AHI, wm, lane);
    const uint32_t aLo = a_lane_base(smb + N_ALO, wm, lane);
    const uint32_t bOff = b_lane_off(wn, lane);
    const uint32_t bufH[2] = {smb + N_B0H, smb + N_B0H + 2 * QB};

    float d[4][4][4];
    #pragma unroll
    for (int f = 0; f < 4; f++)
        #pragma unroll
        for (int g = 0; g < 4; g++)
            #pragma unroll
            for (int c = 0; c < 4; c++) d[f][g][c] = 0.f;

    #pragma unroll 1
    for (int t = 0; t < 16; t++) {
        if (t < 15) {
            int tn = t + 1;
            int nc2 = tn >> 2, qk2 = tn & 3;
            int ch = (qk2 >> 1) * 4 + nc2;
            load_Bq(bufH[tn & 1], bufH[tn & 1] + QB,
                    g_nBhi4 + ch * CHUNK_U4, g_nBlo4 + ch * CHUNK_U4, qk2 & 1, tid);
            cp_wait1();
        } else {
            cp_wait0();
        }
        __syncthreads();
        const int qk = t & 3;
        mma_q(d, aHi + qk * 128, aLo + qk * 128,
              bufH[t & 1] + bOff, bufH[t & 1] + QB + bOff);

        if (qk == 3) {
            const int nc = t >> 2;
            if (nc < 2) {
                #pragma unroll
                for (int g = 0; g < 4; g++) {
                    int col = nc * 128 + wn * 32 + g * 8 + (lane & 3) * 2;
                    float2 bb = *(const float2*)(b1 + col);
                    #pragma unroll
                    for (int f = 0; f < 4; f++) {
                        d[f][g][0] += bb.x; d[f][g][1] += bb.y;
                        d[f][g][2] += bb.x; d[f][g][3] += bb.y;
                    }
                }
            }
            __syncthreads();
            uint32_t* S = (uint32_t*)(sm + N_B0H + (t & 1) * 2 * QB);
            #pragma unroll
            for (int f = 0; f < 4; f++) {
                float m0 = 0.f, m1 = 0.f;
                #pragma unroll
                for (int g = 0; g < 4; g++) {
                    m0 = fmaxf(m0, fmaxf(fabsf(d[f][g][0]), fabsf(d[f][g][1])));
                    m1 = fmaxf(m1, fmaxf(fabsf(d[f][g][2]), fabsf(d[f][g][3])));
                }
                m0 = fmaxf(m0, __shfl_xor_sync(0xFFFFFFFFu, m0, 1));
                m0 = fmaxf(m0, __shfl_xor_sync(0xFFFFFFFFu, m0, 2));
                m1 = fmaxf(m1, __shfl_xor_sync(0xFFFFFFFFu, m1, 1));
                m1 = fmaxf(m1, __shfl_xor_sync(0xFFFFFFFFu, m1, 2));
                float s0 = (m0 > 1e-30f) ? m0 * (1.f / 32704.f) : 1.f;
                float s1 = (m1 > 1e-30f) ? m1 * (1.f / 32704.f) : 1.f;
                float i0 = 1.f / s0, i1 = 1.f / s1;
                int r0 = wm * 64 + f * 16 + (lane >> 2);
                int r1 = r0 + 8;
                if ((lane & 3) == 0) {
                    if (mbase + r0 < N_NODES) g_sc[(mbase + r0) * 16 + nc * 4 + wn] = s0;
                    if (mbase + r1 < N_NODES) g_sc[(mbase + r1) * 16 + nc * 4 + wn] = s1;
                }
                #pragma unroll
                for (int g = 0; g < 4; g++) {
                    int cu = wn * 16 + g * 4 + (lane & 3);
                    S[r0 * SPITCH + cu] = pk16(d[f][g][0] * i0, d[f][g][1] * i0);
                    S[r1 * SPITCH + cu] = pk16(d[f][g][2] * i1, d[f][g][3] * i1);
                    d[f][g][0] = d[f][g][1] = d[f][g][2] = d[f][g][3] = 0.f;
                }
            }
            __syncthreads();
            #pragma unroll
            for (int i = 0; i < 8; i++) {
                int idx = i * 256 + tid;
                int row = idx >> 4, c = idx & 15;
                int node = mbase + row;
                if (node < N_NODES) {
                    const uint32_t* sp = S + row * SPITCH + c * 4;
                    uint4 v = make_uint4(sp[0], sp[1], sp[2], sp[3]);
                    g_UVq4[(size_t)node * 64 + nc * 16 + c] = v;
                }
            }
        }
        __syncthreads();
    }
}

// ---------------------------------------------------------------------------
// edge kernel (R15 structure): gathers int16 UV, streaming output stores
// ---------------------------------------------------------------------------
__global__ void __launch_bounds__(256, 1) edge_mma(const void* __restrict__ EI,
                                                   const float* __restrict__ b2,
                                                   float* __restrict__ out) {
    extern __shared__ char sm[];
    const uint32_t smb = smem_u32(sm);
    int* ssrc = (int*)(sm + E_SRC);
    int* sdst = (int*)(sm + E_DST);
    const int tid = threadIdx.x, lane = tid & 31, wid = tid >> 5;
    const int wm = wid & 1, wn = wid >> 1;
    const int ebase = blockIdx.x * 128;

    // prefetch B quarter 0
    load_Bq(smb + E_B0H, smb + E_B0H + QB, g_eBhi4, g_eBlo4, 0, tid);

    if (tid < 128) {
        int e = ebase + tid;
        long long s = 0, dd = 0;
        if (e < E_EDGES) {
            if (g_idx64) {
                const long long* p = (const long long*)EI;
                s = p[e]; dd = p[e + E_EDGES];
            } else {
                const int* p = (const int*)EI;
                s = p[e]; dd = p[e + E_EDGES];
            }
        }
        ssrc[tid] = min(max((int)s, 0), N_NODES - 1);
        sdst[tid] = min(max((int)dd, 0), N_NODES - 1);
    }
    __syncthreads();

    // --- stage A: gather int16 U'/V, dequant (32-col scales), relu, split ---
    {
        const int lrow = tid >> 3;
        const int j = tid & 7;
        const int jj = j >> 2;
        #pragma unroll 1
        for (int s = 0; s < 4; s++) {
            int row = s * 32 + lrow;
            int src = ssrc[row], dst = sdst[row];
            const uint4* Uq = g_UVq4 + (size_t)src * 64;
            const uint4* Vq = g_UVq4 + (size_t)dst * 64 + 32;
            const float* scU = g_sc + src * 16;
            const float* scV = g_sc + dst * 16 + 8;
            char* ah = sm + E_AHI + row * PITCH_A;
            char* al = sm + E_ALO + row * PITCH_A;
            #pragma unroll
            for (int i = 0; i < 4; i++) {
                int k = j * 8 + i * 64;
                uint4 up = Uq[j + i * 8];
                uint4 vp = Vq[j + i * 8];
                float su = scU[i * 2 + jj];
                float sv = scV[i * 2 + jj];
                float uu[8], vv[8];
                dq8(up, su, uu);
                dq8(vp, sv, vv);
                float h0 = fmaxf(uu[0] + vv[0], 0.f);
                float h1 = fmaxf(uu[1] + vv[1], 0.f);
                float h2 = fmaxf(uu[2] + vv[2], 0.f);
                float h3 = fmaxf(uu[3] + vv[3], 0.f);
                float h4 = fmaxf(uu[4] + vv[4], 0.f);
                float h5 = fmaxf(uu[5] + vv[5], 0.f);
                float h6 = fmaxf(uu[6] + vv[6], 0.f);
                float h7 = fmaxf(uu[7] + vv[7], 0.f);
                uint4 hi, lo;
                split2(h0, h1, hi.x, lo.x);
                split2(h2, h3, hi.y, lo.y);
                split2(h4, h5, hi.z, lo.z);
                split2(h6, h7, hi.w, lo.w);
                *(uint4*)(ah + k * 2) = hi;
                *(uint4*)(al + k * 2) = lo;
            }
        }
    }

    const uint32_t aHi = a_lane_base(smb + E_AHI, wm, lane);
    const uint32_t aLo = a_lane_base(smb + E_ALO, wm, lane);
    const uint32_t bOff = b_lane_off(wn, lane);
    const uint32_t bufH[2] = {smb + E_B0H, smb + E_B0H + 2 * QB};

    float d[4][4][4];
    #pragma unroll
    for (int f = 0; f < 4; f++)
        #pragma unroll
        for (int g = 0; g < 4; g++)
            #pragma unroll
            for (int c = 0; c < 4; c++) d[f][g][c] = 0.f;

    #pragma unroll 1
    for (int t = 0; t < 4; t++) {
        if (t < 3) {
            int tn = t + 1;
            load_Bq(bufH[tn & 1], bufH[tn & 1] + QB,
                    g_eBhi4 + (tn >> 1) * CHUNK_U4, g_eBlo4 + (tn >> 1) * CHUNK_U4,
                    tn & 1, tid);
            cp_wait1();
        } else {
            cp_wait0();
        }
        __syncthreads();
        mma_q(d, aHi + t * 128, aLo + t * 128,
              bufH[t & 1] + bOff, bufH[t & 1] + QB + bOff);
        __syncthreads();
    }

    // --- staged, coalesced epilogue with fused b2; streaming stores so the
    //     256MB output doesn't evict the UVq gather table from L2 ---
    float* stg = (float*)(sm + E_B0H);
    #pragma unroll
    for (int g = 0; g < 4; g++) {
        int col = wn * 32 + g * 8 + (lane & 3) * 2;
        #pragma unroll
        for (int f = 0; f < 4; f++) {
            int r0 = wm * 64 + f * 16 + (lane >> 2);
            *(float2*)(stg + r0 * STG_PITCH + col) = make_float2(d[f][g][0], d[f][g][1]);
            *(float2*)(stg + (r0 + 8) * STG_PITCH + col) = make_float2(d[f][g][2], d[f][g][3]);
        }
    }
    __syncthreads();
    {
        const int c = (tid & 31) * 4;
        float4 bb = *(const float4*)(b2 + c);
        #pragma unroll
        for (int i = 0; i < 16; i++) {
            int idx = i * 256 + tid;
            int row = idx >> 5;
            int e = ebase + row;
            if (e < E_EDGES) {
                float4 v = *(const float4*)(stg + row * STG_PITCH + c);
                float4 o = make_float4(v.x + bb.x, v.y + bb.y, v.z + bb.z, v.w + bb.w);
                __stcs((float4*)(out + (size_t)e * 128 + c), o);
            }
        }
    }
}

// ---------------------------------------------------------------------------
// launch — inputs resolved by unique element counts
// ---------------------------------------------------------------------------
extern "C" void kernel_launch(void* const* d_in, const int* in_sizes, int n_in,
                              void* d_out, int out_size) {
    const float* z = nullptr;
    const void* ei = nullptr;
    const float* W1 = nullptr;
    const float* b1 = nullptr;
    const float* W2 = nullptr;
    const float* b2 = nullptr;
    for (int i = 0; i < n_in; i++) {
        switch (in_sizes[i]) {
            case 25600000: z = (const float*)d_in[i]; break;
            case 1000000:  ei = d_in[i];              break;
            case 131072:   W1 = (const float*)d_in[i]; break;
            case 256:      b1 = (const float*)d_in[i]; break;
            case 32768:    W2 = (const float*)d_in[i]; break;
            case 128:      b2 = (const float*)d_in[i]; break;
            default: break;
        }
    }
    float* out = (float*)d_out;

    cudaFuncSetAttribute(node_mma, cudaFuncAttributeMaxDynamicSharedMemorySize, SM_N);
    cudaFuncSetAttribute(edge_mma, cudaFuncAttributeMaxDynamicSharedMemorySize, SM_E);

    detect_kernel<<<1, 32>>>((const unsigned*)ei);
    prep_kernel<<<640, 256>>>(W1, W2);
    node_mma<<<(N_NODES + 127) / 128, 256, SM_N>>>(z, b1);
    edge_mma<<<(E_EDGES + 127) / 128, 256, SM_E>>>(ei, b2, out);
}